// round 4
// baseline (speedup 1.0000x reference)
#include <cuda_runtime.h>
#include <math_constants.h>

// SPP: out = concat(x, pool5(x), pool9(x), pool13(x)) along channels.
// Cascade: pool9 = pool5(pool5(x)), pool13 = pool5(pool9(x)), each separable.
//
// Layout: one WARP handles TWO (n,c) 32x32 planes. Lanes 0-15 -> plane A,
// lanes 16-31 -> plane B (shuffle width=16 keeps segments independent; OOB
// within a segment returns own value, harmless under max). Each lane owns
// 2 columns x 32 rows as float2 registers.
//
// Horizontal 5-max via pair-max factorization (4 SHFL per warp-row for 2
// plane-rows). Vertical 5-max via register ring. Zero smem, zero barriers.
//
// x: (32, 512, 32, 32) f32 -> out: (32, 2048, 32, 32) f32.

#define NCHAN 512
#define HW 1024
#define PLANES (32 * 512)
#define WARPS_PER_BLK 8
#define PLANES_PER_BLK (WARPS_PER_BLK * 2)

__global__ __launch_bounds__(32 * WARPS_PER_BLK)
void spp_kernel(const float* __restrict__ x, float* __restrict__ out) {
    const int lane = threadIdx.x & 31;
    const int wid  = threadIdx.x >> 5;
    const int sub  = lane >> 4;          // which plane within the warp (0/1)
    const int l    = lane & 15;          // column-pair index: cols 2l, 2l+1

    const int plane = blockIdx.x * PLANES_PER_BLK + wid * 2 + sub; // n*512+c
    const int n = plane >> 9;
    const int c = plane & (NCHAN - 1);

    const float2* __restrict__ xin =
        (const float2*)(x + (size_t)plane * HW) + l;
    float2* __restrict__ ob =
        (float2*)(out + ((size_t)n * (4 * NCHAN) + c) * HW) + l;

    // Lane's 2-column strip, all 32 rows, in registers.
    float2 v[32];
    #pragma unroll
    for (int y = 0; y < 32; ++y) v[y] = xin[y * 16];

    // Pass-through: section 0 of the channel concat.
    #pragma unroll
    for (int y = 0; y < 32; ++y) ob[y * 16] = v[y];

    const unsigned FULL = 0xffffffffu;
    const float NEG = -CUDART_INF_F;

    #pragma unroll
    for (int p = 0; p < 3; ++p) {
        float2* __restrict__ obp = ob + (size_t)(p + 1) * NCHAN * (HW / 2);

        // vertical ring over h-rows: r0=h[y-4] .. r3=h[y-1]
        float2 r0 = {NEG, NEG}, r1 = {NEG, NEG},
               r2 = {NEG, NEG}, r3 = {NEG, NEG};

        #pragma unroll
        for (int y = 0; y < 34; ++y) {
            float2 h;
            if (y < 32) {
                const float a = v[y].x, b = v[y].y;
                const float pm = fmaxf(a, b);
                // width=16: shuffles stay inside this plane's lane segment;
                // OOB-in-segment returns own value (duplicate under max).
                const float lp = __shfl_up_sync  (FULL, pm, 1, 16); // max(la,lb)
                const float lb = __shfl_up_sync  (FULL, b,  1, 16); // col 2l-1
                const float ra = __shfl_down_sync(FULL, a,  1, 16); // col 2l+2
                const float rp = __shfl_down_sync(FULL, pm, 1, 16); // max(ra,rb)
                h.x = fmaxf(fmaxf(lp, pm), ra);   // cols 2l-2 .. 2l+2
                h.y = fmaxf(fmaxf(lb, pm), rp);   // cols 2l-1 .. 2l+3
            } else {
                h.x = NEG; h.y = NEG;             // bottom padding rows
            }

            if (y >= 2) {
                float2 m;
                m.x = fmaxf(fmaxf(fmaxf(r0.x, r1.x), fmaxf(r2.x, r3.x)), h.x);
                m.y = fmaxf(fmaxf(fmaxf(r0.y, r1.y), fmaxf(r2.y, r3.y)), h.y);
                v[y - 2] = m;                     // in-place: feeds next pool
                obp[(y - 2) * 16] = m;
            }

            r0 = r1; r1 = r2; r2 = r3; r3 = h;    // renamed by full unroll
        }
    }
}

extern "C" void kernel_launch(void* const* d_in, const int* in_sizes, int n_in,
                              void* d_out, int out_size) {
    const float* x = (const float*)d_in[0];
    float* out     = (float*)d_out;
    spp_kernel<<<PLANES / PLANES_PER_BLK, 32 * WARPS_PER_BLK>>>(x, out);
}